// round 14
// baseline (speedup 1.0000x reference)
#include <cuda_runtime.h>
#include <math.h>

#define E 128
#define H 8
#define CTXLEN 257
#define THREADS 256
#define TANH_CLIP 10.0f

#define MAXB 1024
#define MAXNC 16          // chunks of 64 nodes, supports N <= 1024
#define CHUNK 64
#define LCHUNK 256        // logits nodes per block

// ---------------- device scratch ----------------
__device__ float g_qk[MAXB * H * E];
__device__ float g_wemb[MAXB * H * E];
__device__ float g_qk2[MAXB * E];
__device__ float g_pm[MAXB * MAXNC * H];
__device__ float g_pl[MAXB * MAXNC * H];
__device__ float g_pw[MAXB * MAXNC * H * E];
__device__ float g_sumexp[MAXB];
__device__ float g_P[E * E];                     // P = Wog @ Wqo
__device__ float g_M3[E * E];                    // M3[f][e] = sum_j Wko[f][j] P[e][j]
__device__ float g_T[H * E * E];                 // Tt[k][f], k = h*128+f'

__device__ __forceinline__ float warp_max(float v) {
    #pragma unroll
    for (int o = 16; o; o >>= 1) v = fmaxf(v, __shfl_xor_sync(0xffffffffu, v, o));
    return v;
}
__device__ __forceinline__ float warp_sum(float v) {
    #pragma unroll
    for (int o = 16; o; o >>= 1) v += __shfl_xor_sync(0xffffffffu, v, o);
    return v;
}

// ---------------- precompute composites ----------------
__global__ __launch_bounds__(128) void k_pre1(const float* __restrict__ Wog,
                                              const float* __restrict__ Wqo) {
    __shared__ float row[E];
    const int i = blockIdx.x, j = threadIdx.x;
    row[j] = Wog[i * E + j];
    __syncthreads();
    float acc = 0.f;
    #pragma unroll 8
    for (int k = 0; k < E; k++) acc = fmaf(row[k], Wqo[k * E + j], acc);
    g_P[i * E + j] = acc;
}

__global__ __launch_bounds__(128) void k_pre2(const float* __restrict__ Wko) {
    __shared__ float row[E];
    const int f = blockIdx.x, e = threadIdx.x;
    row[e] = Wko[f * E + e];
    __syncthreads();
    float acc = 0.f;
    #pragma unroll 8
    for (int j = 0; j < E; j++) acc = fmaf(row[j], g_P[e * E + j], acc);
    g_M3[f * E + e] = acc;
}

__global__ __launch_bounds__(THREADS) void k_pre3(const float* __restrict__ Wvg) {
    __shared__ float m3s[E * 16];
    __shared__ float wvs[E * 16];
    const int h = blockIdx.x, t = threadIdx.x;
    for (int idx = t; idx < E * 16; idx += THREADS) {
        int r = idx >> 4, d = idx & 15;
        m3s[idx] = g_M3[r * E + h * 16 + d];
        wvs[idx] = Wvg[r * E + h * 16 + d];
    }
    __syncthreads();
    const int fp = t & 127, fh = t >> 7;
    float wv[16];
    #pragma unroll
    for (int d = 0; d < 16; d++) wv[d] = wvs[fp * 16 + d];
    for (int f = fh * 64; f < fh * 64 + 64; f++) {
        float acc = 0.f;
        #pragma unroll
        for (int d = 0; d < 16; d++) acc = fmaf(m3s[f * 16 + d], wv[d], acc);
        g_T[(h * E + fp) * E + f] = acc;
    }
}

// ---------------- K1: graph mean + context + q + qk (fused) ----------------
__global__ __launch_bounds__(THREADS) void k_meanctx(
    const float* __restrict__ emb, const float* __restrict__ rc,
    const int* __restrict__ cur,
    const float* __restrict__ Wqg, const float* __restrict__ Wkg, int N)
{
    __shared__ __align__(16) float4 red[THREADS];
    __shared__ __align__(16) float s_ctx[260];   // padded to multiple of 4
    __shared__ __align__(16) float s_sq[256];
    __shared__ __align__(16) float s_q[128];

    const int b = blockIdx.x, t = threadIdx.x, lane = t & 31, warp = t >> 5;
    const float* embB = emb + (size_t)b * N * E;

    // phase 0: mean + current-node + capacity into smem context
    {
        float4 acc = make_float4(0.f, 0.f, 0.f, 0.f);
        #pragma unroll 4
        for (int n = warp; n < N; n += 8) {
            float4 v = *(const float4*)(embB + (size_t)n * E + lane * 4);
            acc.x += v.x; acc.y += v.y; acc.z += v.z; acc.w += v.w;
        }
        red[t] = acc;
        __syncthreads();
        if (warp == 0) {
            float4 s = red[lane];
            #pragma unroll
            for (int r = 1; r < 8; r++) {
                float4 v = red[r * 32 + lane];
                s.x += v.x; s.y += v.y; s.z += v.z; s.w += v.w;
            }
            float invN = 1.0f / (float)N;
            s_ctx[lane * 4 + 0] = s.x * invN;
            s_ctx[lane * 4 + 1] = s.y * invN;
            s_ctx[lane * 4 + 2] = s.z * invN;
            s_ctx[lane * 4 + 3] = s.w * invN;
        } else if (warp == 1) {
            int cn = cur[b];
            float4 v = *(const float4*)(embB + (size_t)cn * E + lane * 4);
            s_ctx[128 + lane * 4 + 0] = v.x;
            s_ctx[128 + lane * 4 + 1] = v.y;
            s_ctx[128 + lane * 4 + 2] = v.z;
            s_ctx[128 + lane * 4 + 3] = v.w;
        }
        if (t == 64) { s_ctx[256] = rc[b]; g_sumexp[b] = 0.f; }
        __syncthreads();
    }

    // phase A: q = ctx @ Wqg (c-range split across half-blocks)
    {
        const int j = t & 127, half = t >> 7;
        const int c0 = half ? 128 : 0;
        const int c1 = half ? CTXLEN : 128;
        float acc = 0.f;
        #pragma unroll 4
        for (int c = c0; c < c1; c++)
            acc = fmaf(s_ctx[c], Wqg[c * E + j], acc);
        s_sq[half * 128 + j] = acc;
    }
    __syncthreads();
    if (t < 128) s_q[t] = s_sq[t] + s_sq[128 + t];
    __syncthreads();

    // phase B: qk[h][f] = sum_d q[h*16+d] * Wkg[f][h*16+d]  (Wkg from L2)
    #pragma unroll
    for (int k = 0; k < 4; k++) {
        int o = k * THREADS + t;
        int h = o >> 7, f = o & 127;
        const float4* wrow = (const float4*)(Wkg + f * E + h * 16);
        const float4* qrow = (const float4*)(s_q + h * 16);
        float a = 0.f;
        #pragma unroll
        for (int j4 = 0; j4 < 4; j4++) {
            float4 w = wrow[j4];
            float4 qq = qrow[j4];
            a = fmaf(w.x, qq.x, a);
            a = fmaf(w.y, qq.y, a);
            a = fmaf(w.z, qq.z, a);
            a = fmaf(w.w, qq.w, a);
        }
        g_qk[b * (H * E) + h * E + f] = a;
    }
}

// ---------------- K3: split-K flash partials (v6: no qk stage, 5 blocks/SM) ----------------
__global__ __launch_bounds__(THREADS, 5) void k_flash(
    const float* __restrict__ emb, const unsigned char* __restrict__ mask, int N)
{
    __shared__ __align__(16) float s_tile[CHUNK * 132];  // 33.8 KB
    __shared__ __align__(16) float s_cp[H * 68];         // compat c, then p (in place)
    __shared__ __align__(16) float s_scr[2048];          // 8 KB combine scratch
    __shared__ unsigned char s_m[CHUNK];

    const int c = blockIdx.x, b = blockIdx.y;
    const int t = threadIdx.x, lane = t & 31, warp = t >> 5;
    const int n0 = c * CHUNK;
    const int cnt = min(CHUNK, N - n0);

    const float* qkB = g_qk + (size_t)b * (H * E);   // read via warp-uniform LDG

    if (t < CHUNK)
        s_m[t] = (t < cnt) ? mask[(size_t)b * N + n0 + t] : (unsigned char)1;

    // tile load, zero-filled beyond cnt
    const float* embB = emb + ((size_t)b * N + n0) * E;
    #pragma unroll
    for (int r = 0; r < 8; r++) {
        int j = r * THREADS + t;
        int i = j >> 5, c4 = j & 31;
        float4 v = make_float4(0.f, 0.f, 0.f, 0.f);
        if (i < cnt) v = *(const float4*)(embB + (size_t)i * E + c4 * 4);
        *(float4*)(s_tile + i * 132 + c4 * 4) = v;
    }
    __syncthreads();

    // compat: warp = ke (k-eighth); thread = 2 nodes, 8 heads in regs.
    // q via warp-uniform LDG.128 (L1-cached, 1 sector/inst).
    {
        const int ke = warp;
        const float4* e0 = (const float4*)(s_tile + lane * 132);
        const float4* e1 = (const float4*)(s_tile + (lane + 32) * 132);
        float a0[8], a1[8];
        #pragma unroll
        for (int h = 0; h < 8; h++) { a0[h] = 0.f; a1[h] = 0.f; }
        #pragma unroll
        for (int ff = 0; ff < 4; ff++) {
            const int f4 = ke * 4 + ff;
            float4 x0 = e0[f4];
            float4 x1 = e1[f4];
            #pragma unroll
            for (int h = 0; h < 8; h++) {
                float4 q4 = *((const float4*)(qkB + h * E) + f4);   // uniform LDG
                a0[h] = fmaf(q4.x, x0.x, a0[h]); a1[h] = fmaf(q4.x, x1.x, a1[h]);
                a0[h] = fmaf(q4.y, x0.y, a0[h]); a1[h] = fmaf(q4.y, x1.y, a1[h]);
                a0[h] = fmaf(q4.z, x0.z, a0[h]); a1[h] = fmaf(q4.z, x1.z, a1[h]);
                a0[h] = fmaf(q4.w, x0.w, a0[h]); a1[h] = fmaf(q4.w, x1.w, a1[h]);
            }
        }
        // park+combine in two head-half rounds through the 8 KB scratch
        #pragma unroll
        for (int rnd = 0; rnd < 2; rnd++) {
            __syncthreads();
            #pragma unroll
            for (int hh = 0; hh < 4; hh++) {
                const int h = rnd * 4 + hh;
                s_scr[ke * 256 + hh * 64 + lane]      = a0[h];
                s_scr[ke * 256 + hh * 64 + lane + 32] = a1[h];
            }
            __syncthreads();
            {
                const int hh = t >> 6, i = t & 63;     // 4 heads x 64 nodes = 256
                float s = 0.f;
                #pragma unroll
                for (int ke2 = 0; ke2 < 8; ke2++)
                    s += s_scr[ke2 * 256 + hh * 64 + i];
                s_cp[(rnd * 4 + hh) * 68 + i] = s_m[i] ? -1e30f : s * 0.25f;
            }
        }
    }
    __syncthreads();

    // softmax partial, in place: warp h reads c, writes p back to s_cp
    {
        const int h = warp;
        float c0 = s_cp[h * 68 + lane];
        float c1 = s_cp[h * 68 + lane + 32];
        float m = warp_max(fmaxf(c0, c1));
        float p0 = __expf(c0 - m);
        float p1 = __expf(c1 - m);
        if (lane >= cnt)      p0 = 0.f;
        if (lane + 32 >= cnt) p1 = 0.f;
        float l = warp_sum(p0 + p1);
        s_cp[h * 68 + lane]      = p0;
        s_cp[h * 68 + lane + 32] = p1;
        const int base = (b * MAXNC + c) * H + h;
        if (lane == 0) { g_pm[base] = m; g_pl[base] = l; }
    }
    __syncthreads();

    // wemb: warp = (hq = head group of 4, qtr = node quarter of 16); lane = fg.
    // final combine stores straight to g_pw from registers (coalesced STG.128)
    {
        const int hq  = warp >> 2;   // heads hq*4 .. hq*4+3
        const int qtr = warp & 3;    // nodes qtr*16 .. +15
        const int fg  = lane;
        float4 acc[4];
        #pragma unroll
        for (int hh = 0; hh < 4; hh++) acc[hh] = make_float4(0.f, 0.f, 0.f, 0.f);

        #pragma unroll
        for (int i4 = 0; i4 < 4; i4++) {
            const int ib = qtr * 16 + i4 * 4;
            float4 p[4];
            #pragma unroll
            for (int hh = 0; hh < 4; hh++)
                p[hh] = *(const float4*)(s_cp + (hq * 4 + hh) * 68 + ib);
            #pragma unroll
            for (int k = 0; k < 4; k++) {
                float4 e4 = *(const float4*)(s_tile + (ib + k) * 132 + fg * 4);
                #pragma unroll
                for (int hh = 0; hh < 4; hh++) {
                    float pv = (k == 0) ? p[hh].x : (k == 1) ? p[hh].y
                             : (k == 2) ? p[hh].z : p[hh].w;
                    acc[hh].x = fmaf(pv, e4.x, acc[hh].x);
                    acc[hh].y = fmaf(pv, e4.y, acc[hh].y);
                    acc[hh].z = fmaf(pv, e4.z, acc[hh].z);
                    acc[hh].w = fmaf(pv, e4.w, acc[hh].w);
                }
            }
        }

        // round 1: quarters 2,3 park; 0,1 accumulate
        if (qtr >= 2) {
            float4* dst = (float4*)s_scr + (hq * 2 + (qtr - 2)) * 128;
            #pragma unroll
            for (int hh = 0; hh < 4; hh++) dst[hh * 32 + fg] = acc[hh];
        }
        __syncthreads();
        if (qtr < 2) {
            const float4* src = (const float4*)s_scr + (hq * 2 + qtr) * 128;
            #pragma unroll
            for (int hh = 0; hh < 4; hh++) {
                float4 r = src[hh * 32 + fg];
                acc[hh].x += r.x; acc[hh].y += r.y;
                acc[hh].z += r.z; acc[hh].w += r.w;
            }
        }
        __syncthreads();
        // round 2: quarter 1 parks; quarter 0 finalizes + STG direct
        if (qtr == 1) {
            float4* dst = (float4*)s_scr + hq * 128;
            #pragma unroll
            for (int hh = 0; hh < 4; hh++) dst[hh * 32 + fg] = acc[hh];
        }
        __syncthreads();
        if (qtr == 0) {
            const float4* src = (const float4*)s_scr + hq * 128;
            float* dstg = g_pw + (size_t)(b * MAXNC + c) * (H * E);
            #pragma unroll
            for (int hh = 0; hh < 4; hh++) {
                float4 r = src[hh * 32 + fg];
                acc[hh].x += r.x; acc[hh].y += r.y;
                acc[hh].z += r.z; acc[hh].w += r.w;
                *(float4*)(dstg + (hq * 4 + hh) * E + fg * 4) = acc[hh];
            }
        }
    }
}

// ---------------- K4a: combine partials -> normalized wemb ----------------
__global__ __launch_bounds__(THREADS) void k_norm(int nchunk) {
    const int b = blockIdx.x, t = threadIdx.x, lane = t & 31, h = t >> 5;
    float m = -1e30f;
    for (int c = 0; c < nchunk; c++)
        m = fmaxf(m, g_pm[(b * MAXNC + c) * H + h]);
    float L = 0.f;
    float4 w = make_float4(0.f, 0.f, 0.f, 0.f);
    for (int c = 0; c < nchunk; c++) {
        const int base = (b * MAXNC + c) * H + h;
        float s = __expf(g_pm[base] - m);
        L = fmaf(s, g_pl[base], L);
        float4 pw = *(const float4*)(g_pw + (size_t)(b * MAXNC + c) * (H * E) + h * E + lane * 4);
        w.x = fmaf(s, pw.x, w.x); w.y = fmaf(s, pw.y, w.y);
        w.z = fmaf(s, pw.z, w.z); w.w = fmaf(s, pw.w, w.w);
    }
    float invL = 1.0f / L;
    float* d = g_wemb + b * (H * E) + h * E + lane * 4;
    d[0] = w.x * invL; d[1] = w.y * invL; d[2] = w.z * invL; d[3] = w.w * invL;
}

// ---------------- K4b: qk2 = wemb @ Tt (aligned, conflict-aware) ----------------
// smem: sg[8192] wemb as [k][8] (32B-aligned per k) | red[2048] -> 10240 floats
__global__ __launch_bounds__(THREADS) void k_gemm(int B) {
    extern __shared__ float sg[];
    float* red = sg + 8192;
    const int b0 = blockIdx.x * 8, t = threadIdx.x;

    for (int idx = t; idx < 8192; idx += THREADS) {
        int bb = idx >> 10, k = idx & 1023;
        sg[k * 8 + bb] = g_wemb[(size_t)(b0 + bb) * (H * E) + k];
    }
    __syncthreads();

    const int f = t & 127, half = t >> 7;
    float acc[8];
    #pragma unroll
    for (int i = 0; i < 8; i++) acc[i] = 0.f;

    const int k0 = half * 512;
    #pragma unroll 4
    for (int k = k0; k < k0 + 512; k++) {
        float tv = g_T[(size_t)k * E + f];          // coalesced, L2-resident
        float wq[8];
        *(float4*)(wq)     = *(const float4*)(sg + k * 8);      // broadcast
        *(float4*)(wq + 4) = *(const float4*)(sg + k * 8 + 4);  // broadcast
        #pragma unroll
        for (int bb = 0; bb < 8; bb++)
            acc[bb] = fmaf(tv, wq[bb], acc[bb]);
    }

    #pragma unroll
    for (int bb = 0; bb < 8; bb++)
        red[half * 1024 + bb * 128 + f] = acc[bb];  // f in low bits: conflict-free
    __syncthreads();

    #pragma unroll
    for (int j = 0; j < 4; j++) {
        int o = t + j * 256;
        int bb = o >> 7, ff = o & 127;
        float s = red[o] + red[1024 + o];
        if (b0 + bb < B) g_qk2[(size_t)(b0 + bb) * E + ff] = s;
    }
}

// ---------------- K5: logits + sumexp (two-phase smem reduce) ----------------
__global__ __launch_bounds__(THREADS) void k_logits(
    const float* __restrict__ emb, const unsigned char* __restrict__ mask,
    float* __restrict__ out, int N, int B)
{
    const int cblk = blockIdx.x, b = blockIdx.y;
    const int t = threadIdx.x, lane = t & 31, warp = t >> 5;
    const int n0 = cblk * LCHUNK;

    __shared__ float s_part[LCHUNK * 33];   // padded
    __shared__ float s_sum[8];

    float4 qv = *(const float4*)(g_qk2 + b * E + lane * 4);
    const float* embB = emb + (size_t)b * N * E;
    const size_t BN = (size_t)B * N;

    // phase 1: warp w covers nodes n0 + w*32 + k, k = 0..31
    #pragma unroll 4
    for (int k = 0; k < 32; k++) {
        const int nl = warp * 32 + k;
        const int n = n0 + nl;
        float p = 0.f;
        if (n < N) {
            float4 e4 = *(const float4*)(embB + (size_t)n * E + lane * 4);
            p = e4.x * qv.x;
            p = fmaf(e4.y, qv.y, p);
            p = fmaf(e4.z, qv.z, p);
            p = fmaf(e4.w, qv.w, p);
        }
        s_part[nl * 33 + lane] = p;
    }
    __syncthreads();

    // phase 2: thread t handles node n0 + t
    const float inv_sqrtE = 0.08838834764831845f;  // 1/sqrt(128)
    float lsum = 0.f;
    {
        const int n = n0 + t;
        if (n < N) {
            float s0 = 0.f, s1 = 0.f, s2 = 0.f, s3 = 0.f;
            #pragma unroll
            for (int j = 0; j < 32; j += 4) {
                s0 += s_part[t * 33 + j];
                s1 += s_part[t * 33 + j + 1];
                s2 += s_part[t * 33 + j + 2];
                s3 += s_part[t * 33 + j + 3];
            }
            float d = (s0 + s1) + (s2 + s3);
            float x = d * inv_sqrtE;
            x = fminf(fmaxf(x, -15.f), 15.f);
            float ex = __expf(2.f * x);
            float lg = TANH_CLIP * (ex - 1.f) / (ex + 1.f);
            if (mask[(size_t)b * N + n]) lg = -INFINITY;
            out[BN + (size_t)b * N + n] = lg;
            lsum = __expf(lg - TANH_CLIP);
        }
    }
    lsum = warp_sum(lsum);
    if (lane == 0) s_sum[warp] = lsum;
    __syncthreads();
    if (t == 0) {
        float s = 0.f;
        #pragma unroll
        for (int w = 0; w < 8; w++) s += s_sum[w];
        atomicAdd(&g_sumexp[b], s);
    }
}

// ---------------- K6: probs ----------------
__global__ __launch_bounds__(THREADS) void k_probs(float* __restrict__ out, int N, int B) {
    const int b = blockIdx.x, t = threadIdx.x;
    const size_t BN = (size_t)B * N;
    float inv = 1.0f / g_sumexp[b];
    for (int n = t; n < N; n += THREADS) {
        float lg = out[BN + (size_t)b * N + n];
        out[(size_t)b * N + n] = __expf(lg - TANH_CLIP) * inv;
    }
}

// ---------------- launch ----------------
extern "C" void kernel_launch(void* const* d_in, const int* in_sizes, int n_in,
                              void* d_out, int out_size) {
    const float* emb = (const float*)d_in[0];
    const float* rc  = (const float*)d_in[1];
    const float* Wqg = (const float*)d_in[2];
    const float* Wkg = (const float*)d_in[3];
    const float* Wvg = (const float*)d_in[4];
    const float* Wog = (const float*)d_in[5];
    const float* Wqo = (const float*)d_in[6];
    const float* Wko = (const float*)d_in[7];
    const int*   cur = (const int*)d_in[8];
    const unsigned char* mask = (const unsigned char*)d_in[9];

    int B = in_sizes[1];
    int N = in_sizes[0] / (B * E);
    float* out = (float*)d_out;

    int nchunk  = (N + CHUNK - 1) / CHUNK;
    int nlchunk = (N + LCHUNK - 1) / LCHUNK;
    int ngemm   = (B + 7) / 8;

    static bool attr_done = false;
    if (!attr_done) {
        cudaFuncSetAttribute(k_gemm, cudaFuncAttributeMaxDynamicSharedMemorySize,
                             10240 * (int)sizeof(float));
        attr_done = true;
    }

    // Order: k_flash stays the 4th launch (ncu capture slot).
    k_pre1<<<E, 128>>>(Wog, Wqo);
    k_meanctx<<<B, THREADS>>>(emb, rc, cur, Wqg, Wkg, N);
    k_pre2<<<E, 128>>>(Wko);
    k_flash<<<dim3(nchunk, B), THREADS>>>(emb, mask, N);
    k_pre3<<<H, THREADS>>>(Wvg);
    k_norm<<<B, THREADS>>>(nchunk);
    k_gemm<<<ngemm, THREADS, 10240 * sizeof(float)>>>(B);
    k_logits<<<dim3(nlchunk, B), THREADS>>>(emb, mask, out, N, B);
    k_probs<<<B, THREADS>>>(out, N, B);
}

// round 15
// speedup vs baseline: 1.0394x; 1.0394x over previous
#include <cuda_runtime.h>
#include <math.h>

#define E 128
#define H 8
#define CTXLEN 257
#define THREADS 256
#define TANH_CLIP 10.0f

#define MAXB 1024
#define MAXNC 16          // chunks of 64 nodes, supports N <= 1024
#define CHUNK 64
#define LCHUNK 256        // logits nodes per block

// ---------------- device scratch ----------------
__device__ float g_qk[MAXB * H * E];
__device__ float g_wemb[MAXB * H * E];
__device__ float g_qk2[MAXB * E];
__device__ float g_pm[MAXB * MAXNC * H];
__device__ float g_pl[MAXB * MAXNC * H];
__device__ float g_pw[MAXB * MAXNC * H * E];
__device__ float g_sumexp[MAXB];
__device__ float g_P[E * E];                     // P = Wog @ Wqo
__device__ float g_M3[E * E];                    // M3[f][e] = sum_j Wko[f][j] P[e][j]
__device__ float g_T[H * E * E];                 // Tt[k][f], k = h*128+f'

__device__ __forceinline__ float warp_max(float v) {
    #pragma unroll
    for (int o = 16; o; o >>= 1) v = fmaxf(v, __shfl_xor_sync(0xffffffffu, v, o));
    return v;
}
__device__ __forceinline__ float warp_sum(float v) {
    #pragma unroll
    for (int o = 16; o; o >>= 1) v += __shfl_xor_sync(0xffffffffu, v, o);
    return v;
}

// ---------------- precompute composites ----------------
__global__ __launch_bounds__(128) void k_pre1(const float* __restrict__ Wog,
                                              const float* __restrict__ Wqo) {
    __shared__ float row[E];
    const int i = blockIdx.x, j = threadIdx.x;
    row[j] = Wog[i * E + j];
    __syncthreads();
    float acc = 0.f;
    #pragma unroll 8
    for (int k = 0; k < E; k++) acc = fmaf(row[k], Wqo[k * E + j], acc);
    g_P[i * E + j] = acc;
}

__global__ __launch_bounds__(128) void k_pre2(const float* __restrict__ Wko) {
    __shared__ float row[E];
    const int f = blockIdx.x, e = threadIdx.x;
    row[e] = Wko[f * E + e];
    __syncthreads();
    float acc = 0.f;
    #pragma unroll 8
    for (int j = 0; j < E; j++) acc = fmaf(row[j], g_P[e * E + j], acc);
    g_M3[f * E + e] = acc;
}

__global__ __launch_bounds__(THREADS) void k_pre3(const float* __restrict__ Wvg) {
    __shared__ float m3s[E * 16];
    __shared__ float wvs[E * 16];
    const int h = blockIdx.x, t = threadIdx.x;
    for (int idx = t; idx < E * 16; idx += THREADS) {
        int r = idx >> 4, d = idx & 15;
        m3s[idx] = g_M3[r * E + h * 16 + d];
        wvs[idx] = Wvg[r * E + h * 16 + d];
    }
    __syncthreads();
    const int fp = t & 127, fh = t >> 7;
    float wv[16];
    #pragma unroll
    for (int d = 0; d < 16; d++) wv[d] = wvs[fp * 16 + d];
    for (int f = fh * 64; f < fh * 64 + 64; f++) {
        float acc = 0.f;
        #pragma unroll
        for (int d = 0; d < 16; d++) acc = fmaf(m3s[f * 16 + d], wv[d], acc);
        g_T[(h * E + fp) * E + f] = acc;
    }
}

// ---------------- K1: graph mean + context + q + qk (fused) ----------------
__global__ __launch_bounds__(THREADS) void k_meanctx(
    const float* __restrict__ emb, const float* __restrict__ rc,
    const int* __restrict__ cur,
    const float* __restrict__ Wqg, const float* __restrict__ Wkg, int N)
{
    __shared__ __align__(16) float4 red[THREADS];
    __shared__ __align__(16) float s_ctx[260];   // padded to multiple of 4
    __shared__ __align__(16) float s_sq[256];
    __shared__ __align__(16) float s_q[128];

    const int b = blockIdx.x, t = threadIdx.x, lane = t & 31, warp = t >> 5;
    const float* embB = emb + (size_t)b * N * E;

    // phase 0: mean + current-node + capacity into smem context
    {
        float4 acc = make_float4(0.f, 0.f, 0.f, 0.f);
        #pragma unroll 4
        for (int n = warp; n < N; n += 8) {
            float4 v = *(const float4*)(embB + (size_t)n * E + lane * 4);
            acc.x += v.x; acc.y += v.y; acc.z += v.z; acc.w += v.w;
        }
        red[t] = acc;
        __syncthreads();
        if (warp == 0) {
            float4 s = red[lane];
            #pragma unroll
            for (int r = 1; r < 8; r++) {
                float4 v = red[r * 32 + lane];
                s.x += v.x; s.y += v.y; s.z += v.z; s.w += v.w;
            }
            float invN = 1.0f / (float)N;
            s_ctx[lane * 4 + 0] = s.x * invN;
            s_ctx[lane * 4 + 1] = s.y * invN;
            s_ctx[lane * 4 + 2] = s.z * invN;
            s_ctx[lane * 4 + 3] = s.w * invN;
        } else if (warp == 1) {
            int cn = cur[b];
            float4 v = *(const float4*)(embB + (size_t)cn * E + lane * 4);
            s_ctx[128 + lane * 4 + 0] = v.x;
            s_ctx[128 + lane * 4 + 1] = v.y;
            s_ctx[128 + lane * 4 + 2] = v.z;
            s_ctx[128 + lane * 4 + 3] = v.w;
        }
        if (t == 64) { s_ctx[256] = rc[b]; g_sumexp[b] = 0.f; }
        __syncthreads();
    }

    // phase A: q = ctx @ Wqg (c-range split across half-blocks; 2 FMA chains)
    {
        const int j = t & 127, half = t >> 7;
        const int c0 = half ? 128 : 0;
        const int c1 = half ? 256 : 128;
        float acc0 = 0.f, acc1 = 0.f;
        #pragma unroll 4
        for (int c = c0; c < c1; c += 2) {
            acc0 = fmaf(s_ctx[c],     Wqg[c * E + j],       acc0);
            acc1 = fmaf(s_ctx[c + 1], Wqg[(c + 1) * E + j], acc1);
        }
        if (half) acc0 = fmaf(s_ctx[256], Wqg[256 * E + j], acc0);  // c = 256
        s_sq[half * 128 + j] = acc0 + acc1;
    }
    __syncthreads();
    if (t < 128) s_q[t] = s_sq[t] + s_sq[128 + t];
    __syncthreads();

    // phase B: qk[h][f] = sum_d q[h*16+d] * Wkg[f][h*16+d]  (Wkg from L2)
    #pragma unroll
    for (int k = 0; k < 4; k++) {
        int o = k * THREADS + t;
        int h = o >> 7, f = o & 127;
        const float4* wrow = (const float4*)(Wkg + f * E + h * 16);
        const float4* qrow = (const float4*)(s_q + h * 16);
        float a = 0.f;
        #pragma unroll
        for (int j4 = 0; j4 < 4; j4++) {
            float4 w = wrow[j4];
            float4 qq = qrow[j4];
            a = fmaf(w.x, qq.x, a);
            a = fmaf(w.y, qq.y, a);
            a = fmaf(w.z, qq.z, a);
            a = fmaf(w.w, qq.w, a);
        }
        g_qk[b * (H * E) + h * E + f] = a;
    }
}

// ---------------- K3: split-K flash partials (R13 proven version) ----------------
__global__ __launch_bounds__(THREADS, 4) void k_flash(
    const float* __restrict__ emb, const unsigned char* __restrict__ mask, int N)
{
    __shared__ __align__(16) float s_tile[CHUNK * 132];  // 33.8 KB
    __shared__ __align__(16) float s_qk[H * 132];        // qk in; wemb out
    __shared__ __align__(16) float s_cp[H * 68];         // compat c, then p (in place)
    __shared__ __align__(16) float s_scr[2048];          // 8 KB combine scratch
    __shared__ unsigned char s_m[CHUNK];

    const int c = blockIdx.x, b = blockIdx.y;
    const int t = threadIdx.x, lane = t & 31, warp = t >> 5;
    const int n0 = c * CHUNK;
    const int cnt = min(CHUNK, N - n0);

    // stage qk: one float4 per thread (g_qk row-major [h*128+f] == t*4)
    {
        float4 v = *(const float4*)(g_qk + (size_t)b * (H * E) + t * 4);
        *(float4*)(s_qk + (t >> 5) * 132 + (t & 31) * 4) = v;
    }
    if (t < CHUNK)
        s_m[t] = (t < cnt) ? mask[(size_t)b * N + n0 + t] : (unsigned char)1;

    // tile load, zero-filled beyond cnt
    const float* embB = emb + ((size_t)b * N + n0) * E;
    #pragma unroll
    for (int r = 0; r < 8; r++) {
        int j = r * THREADS + t;
        int i = j >> 5, c4 = j & 31;
        float4 v = make_float4(0.f, 0.f, 0.f, 0.f);
        if (i < cnt) v = *(const float4*)(embB + (size_t)i * E + c4 * 4);
        *(float4*)(s_tile + i * 132 + c4 * 4) = v;
    }
    __syncthreads();

    // compat v5: warp = ke (k-eighth = 4 f4 groups); thread = 2 nodes, 8 heads in regs.
    {
        const int ke = warp;
        const float4* e0 = (const float4*)(s_tile + lane * 132);
        const float4* e1 = (const float4*)(s_tile + (lane + 32) * 132);
        float a0[8], a1[8];
        #pragma unroll
        for (int h = 0; h < 8; h++) { a0[h] = 0.f; a1[h] = 0.f; }
        #pragma unroll
        for (int ff = 0; ff < 4; ff++) {
            const int f4 = ke * 4 + ff;
            float4 x0 = e0[f4];
            float4 x1 = e1[f4];
            #pragma unroll
            for (int h = 0; h < 8; h++) {
                float4 q4 = *((const float4*)(s_qk + h * 132) + f4);   // broadcast
                a0[h] = fmaf(q4.x, x0.x, a0[h]); a1[h] = fmaf(q4.x, x1.x, a1[h]);
                a0[h] = fmaf(q4.y, x0.y, a0[h]); a1[h] = fmaf(q4.y, x1.y, a1[h]);
                a0[h] = fmaf(q4.z, x0.z, a0[h]); a1[h] = fmaf(q4.z, x1.z, a1[h]);
                a0[h] = fmaf(q4.w, x0.w, a0[h]); a1[h] = fmaf(q4.w, x1.w, a1[h]);
            }
        }
        // park+combine in two head-half rounds through the 8 KB scratch
        #pragma unroll
        for (int rnd = 0; rnd < 2; rnd++) {
            __syncthreads();
            #pragma unroll
            for (int hh = 0; hh < 4; hh++) {
                const int h = rnd * 4 + hh;
                s_scr[ke * 256 + hh * 64 + lane]      = a0[h];
                s_scr[ke * 256 + hh * 64 + lane + 32] = a1[h];
            }
            __syncthreads();
            {
                const int hh = t >> 6, i = t & 63;     // 4 heads x 64 nodes = 256
                float s = 0.f;
                #pragma unroll
                for (int ke2 = 0; ke2 < 8; ke2++)
                    s += s_scr[ke2 * 256 + hh * 64 + i];
                s_cp[(rnd * 4 + hh) * 68 + i] = s_m[i] ? -1e30f : s * 0.25f;
            }
        }
    }
    __syncthreads();

    // softmax partial, in place: warp h reads c, writes p back to s_cp
    {
        const int h = warp;
        float c0 = s_cp[h * 68 + lane];
        float c1 = s_cp[h * 68 + lane + 32];
        float m = warp_max(fmaxf(c0, c1));
        float p0 = __expf(c0 - m);
        float p1 = __expf(c1 - m);
        if (lane >= cnt)      p0 = 0.f;
        if (lane + 32 >= cnt) p1 = 0.f;
        float l = warp_sum(p0 + p1);
        s_cp[h * 68 + lane]      = p0;
        s_cp[h * 68 + lane + 32] = p1;
        const int base = (b * MAXNC + c) * H + h;
        if (lane == 0) { g_pm[base] = m; g_pl[base] = l; }
    }
    __syncthreads();

    // wemb: warp = (hq = head group of 4, qtr = node quarter of 16); lane = fg.
    {
        const int hq  = warp >> 2;   // heads hq*4 .. hq*4+3
        const int qtr = warp & 3;    // nodes qtr*16 .. +15
        const int fg  = lane;
        float4 acc[4];
        #pragma unroll
        for (int hh = 0; hh < 4; hh++) acc[hh] = make_float4(0.f, 0.f, 0.f, 0.f);

        #pragma unroll
        for (int i4 = 0; i4 < 4; i4++) {
            const int ib = qtr * 16 + i4 * 4;
            float4 p[4];
            #pragma unroll
            for (int hh = 0; hh < 4; hh++)
                p[hh] = *(const float4*)(s_cp + (hq * 4 + hh) * 68 + ib);
            #pragma unroll
            for (int k = 0; k < 4; k++) {
                float4 e4 = *(const float4*)(s_tile + (ib + k) * 132 + fg * 4);
                #pragma unroll
                for (int hh = 0; hh < 4; hh++) {
                    float pv = (k == 0) ? p[hh].x : (k == 1) ? p[hh].y
                             : (k == 2) ? p[hh].z : p[hh].w;
                    acc[hh].x = fmaf(pv, e4.x, acc[hh].x);
                    acc[hh].y = fmaf(pv, e4.y, acc[hh].y);
                    acc[hh].z = fmaf(pv, e4.z, acc[hh].z);
                    acc[hh].w = fmaf(pv, e4.w, acc[hh].w);
                }
            }
        }

        // round 1: quarters 2,3 park; 0,1 accumulate
        if (qtr >= 2) {
            float4* dst = (float4*)s_scr + (hq * 2 + (qtr - 2)) * 128;
            #pragma unroll
            for (int hh = 0; hh < 4; hh++) dst[hh * 32 + fg] = acc[hh];
        }
        __syncthreads();
        if (qtr < 2) {
            const float4* src = (const float4*)s_scr + (hq * 2 + qtr) * 128;
            #pragma unroll
            for (int hh = 0; hh < 4; hh++) {
                float4 r = src[hh * 32 + fg];
                acc[hh].x += r.x; acc[hh].y += r.y;
                acc[hh].z += r.z; acc[hh].w += r.w;
            }
        }
        __syncthreads();
        // round 2: quarter 1 parks; quarter 0 finalizes
        if (qtr == 1) {
            float4* dst = (float4*)s_scr + hq * 128;
            #pragma unroll
            for (int hh = 0; hh < 4; hh++) dst[hh * 32 + fg] = acc[hh];
        }
        __syncthreads();
        if (qtr == 0) {
            const float4* src = (const float4*)s_scr + hq * 128;
            #pragma unroll
            for (int hh = 0; hh < 4; hh++) {
                float4 r = src[hh * 32 + fg];
                acc[hh].x += r.x; acc[hh].y += r.y;
                acc[hh].z += r.z; acc[hh].w += r.w;
                *(float4*)(s_qk + (hq * 4 + hh) * 132 + fg * 4) = acc[hh];
            }
        }
    }
    __syncthreads();

    // store g_pw: one float4 per thread
    *(float4*)(g_pw + (size_t)(b * MAXNC + c) * (H * E) + t * 4) =
        *(const float4*)(s_qk + (t >> 5) * 132 + (t & 31) * 4);
}

// ---------------- K4a: combine partials -> normalized wemb ----------------
__global__ __launch_bounds__(THREADS) void k_norm(int nchunk) {
    const int b = blockIdx.x, t = threadIdx.x, lane = t & 31, h = t >> 5;
    float m = -1e30f;
    for (int c = 0; c < nchunk; c++)
        m = fmaxf(m, g_pm[(b * MAXNC + c) * H + h]);
    float L = 0.f;
    float4 w = make_float4(0.f, 0.f, 0.f, 0.f);
    for (int c = 0; c < nchunk; c++) {
        const int base = (b * MAXNC + c) * H + h;
        float s = __expf(g_pm[base] - m);
        L = fmaf(s, g_pl[base], L);
        float4 pw = *(const float4*)(g_pw + (size_t)(b * MAXNC + c) * (H * E) + h * E + lane * 4);
        w.x = fmaf(s, pw.x, w.x); w.y = fmaf(s, pw.y, w.y);
        w.z = fmaf(s, pw.z, w.z); w.w = fmaf(s, pw.w, w.w);
    }
    float invL = 1.0f / L;
    float* d = g_wemb + b * (H * E) + h * E + lane * 4;
    d[0] = w.x * invL; d[1] = w.y * invL; d[2] = w.z * invL; d[3] = w.w * invL;
}

// ---------------- K4b: qk2 = wemb @ Tt (aligned, conflict-aware) ----------------
// smem: sg[8192] wemb as [k][8] (32B-aligned per k) | red[2048] -> 10240 floats
__global__ __launch_bounds__(THREADS) void k_gemm(int B) {
    extern __shared__ float sg[];
    float* red = sg + 8192;
    const int b0 = blockIdx.x * 8, t = threadIdx.x;

    for (int idx = t; idx < 8192; idx += THREADS) {
        int bb = idx >> 10, k = idx & 1023;
        sg[k * 8 + bb] = g_wemb[(size_t)(b0 + bb) * (H * E) + k];
    }
    __syncthreads();

    const int f = t & 127, half = t >> 7;
    float acc[8];
    #pragma unroll
    for (int i = 0; i < 8; i++) acc[i] = 0.f;

    const int k0 = half * 512;
    #pragma unroll 4
    for (int k = k0; k < k0 + 512; k++) {
        float tv = g_T[(size_t)k * E + f];          // coalesced, L2-resident
        float wq[8];
        *(float4*)(wq)     = *(const float4*)(sg + k * 8);      // broadcast
        *(float4*)(wq + 4) = *(const float4*)(sg + k * 8 + 4);  // broadcast
        #pragma unroll
        for (int bb = 0; bb < 8; bb++)
            acc[bb] = fmaf(tv, wq[bb], acc[bb]);
    }

    #pragma unroll
    for (int bb = 0; bb < 8; bb++)
        red[half * 1024 + bb * 128 + f] = acc[bb];  // f in low bits: conflict-free
    __syncthreads();

    #pragma unroll
    for (int j = 0; j < 4; j++) {
        int o = t + j * 256;
        int bb = o >> 7, ff = o & 127;
        float s = red[o] + red[1024 + o];
        if (b0 + bb < B) g_qk2[(size_t)(b0 + bb) * E + ff] = s;
    }
}

// ---------------- K5: logits + sumexp (two-phase smem reduce) ----------------
__global__ __launch_bounds__(THREADS) void k_logits(
    const float* __restrict__ emb, const unsigned char* __restrict__ mask,
    float* __restrict__ out, int N, int B)
{
    const int cblk = blockIdx.x, b = blockIdx.y;
    const int t = threadIdx.x, lane = t & 31, warp = t >> 5;
    const int n0 = cblk * LCHUNK;

    __shared__ float s_part[LCHUNK * 33];   // padded
    __shared__ float s_sum[8];

    float4 qv = *(const float4*)(g_qk2 + b * E + lane * 4);
    const float* embB = emb + (size_t)b * N * E;
    const size_t BN = (size_t)B * N;

    // phase 1: warp w covers nodes n0 + w*32 + k, k = 0..31
    #pragma unroll 8
    for (int k = 0; k < 32; k++) {
        const int nl = warp * 32 + k;
        const int n = n0 + nl;
        float p = 0.f;
        if (n < N) {
            float4 e4 = *(const float4*)(embB + (size_t)n * E + lane * 4);
            p = e4.x * qv.x;
            p = fmaf(e4.y, qv.y, p);
            p = fmaf(e4.z, qv.z, p);
            p = fmaf(e4.w, qv.w, p);
        }
        s_part[nl * 33 + lane] = p;
    }
    __syncthreads();

    // phase 2: thread t handles node n0 + t
    const float inv_sqrtE = 0.08838834764831845f;  // 1/sqrt(128)
    float lsum = 0.f;
    {
        const int n = n0 + t;
        if (n < N) {
            float s0 = 0.f, s1 = 0.f, s2 = 0.f, s3 = 0.f;
            #pragma unroll
            for (int j = 0; j < 32; j += 4) {
                s0 += s_part[t * 33 + j];
                s1 += s_part[t * 33 + j + 1];
                s2 += s_part[t * 33 + j + 2];
                s3 += s_part[t * 33 + j + 3];
            }
            float d = (s0 + s1) + (s2 + s3);
            float x = d * inv_sqrtE;
            x = fminf(fmaxf(x, -15.f), 15.f);
            float ex = __expf(2.f * x);
            float lg = TANH_CLIP * (ex - 1.f) / (ex + 1.f);
            if (mask[(size_t)b * N + n]) lg = -INFINITY;
            out[BN + (size_t)b * N + n] = lg;
            lsum = __expf(lg - TANH_CLIP);
        }
    }
    lsum = warp_sum(lsum);
    if (lane == 0) s_sum[warp] = lsum;
    __syncthreads();
    if (t == 0) {
        float s = 0.f;
        #pragma unroll
        for (int w = 0; w < 8; w++) s += s_sum[w];
        atomicAdd(&g_sumexp[b], s);
    }
}

// ---------------- K6: probs ----------------
__global__ __launch_bounds__(THREADS) void k_probs(float* __restrict__ out, int N, int B) {
    const int b = blockIdx.x, t = threadIdx.x;
    const size_t BN = (size_t)B * N;
    float inv = 1.0f / g_sumexp[b];
    for (int n = t; n < N; n += THREADS) {
        float lg = out[BN + (size_t)b * N + n];
        out[(size_t)b * N + n] = __expf(lg - TANH_CLIP) * inv;
    }
}

// ---------------- launch ----------------
extern "C" void kernel_launch(void* const* d_in, const int* in_sizes, int n_in,
                              void* d_out, int out_size) {
    const float* emb = (const float*)d_in[0];
    const float* rc  = (const float*)d_in[1];
    const float* Wqg = (const float*)d_in[2];
    const float* Wkg = (const float*)d_in[3];
    const float* Wvg = (const float*)d_in[4];
    const float* Wog = (const float*)d_in[5];
    const float* Wqo = (const float*)d_in[6];
    const float* Wko = (const float*)d_in[7];
    const int*   cur = (const int*)d_in[8];
    const unsigned char* mask = (const unsigned char*)d_in[9];

    int B = in_sizes[1];
    int N = in_sizes[0] / (B * E);
    float* out = (float*)d_out;

    int nchunk  = (N + CHUNK - 1) / CHUNK;
    int nlchunk = (N + LCHUNK - 1) / LCHUNK;
    int ngemm   = (B + 7) / 8;

    static bool attr_done = false;
    if (!attr_done) {
        cudaFuncSetAttribute(k_gemm, cudaFuncAttributeMaxDynamicSharedMemorySize,
                             10240 * (int)sizeof(float));
        attr_done = true;
    }

    // Order: k_meanctx is the 4th launch (ncu capture slot) this round.
    k_pre1<<<E, 128>>>(Wog, Wqo);
    k_pre2<<<E, 128>>>(Wko);
    k_pre3<<<H, THREADS>>>(Wvg);
    k_meanctx<<<B, THREADS>>>(emb, rc, cur, Wqg, Wkg, N);
    k_flash<<<dim3(nchunk, B), THREADS>>>(emb, mask, N);
    k_norm<<<B, THREADS>>>(nchunk);
    k_gemm<<<ngemm, THREADS, 10240 * sizeof(float)>>>(B);
    k_logits<<<dim3(nlchunk, B), THREADS>>>(emb, mask, out, N, B);
    k_probs<<<B, THREADS>>>(out, N, B);
}